// round 11
// baseline (speedup 1.0000x reference)
#include <cuda_runtime.h>
#include <cuda_bf16.h>
#include <math.h>

#define B 64
#define F 32

typedef unsigned long long u64;

__device__ __align__(128) float g_f128[(size_t)B * F * 128 * 128];
__device__ __align__(128) float g_bufA[(size_t)B * F * 64 * 64];
__device__ __align__(128) float g_bufB[(size_t)B * F * 64 * 64];
__device__ __align__(128) float g_bufC[(size_t)B * F * 64 * 64];
__device__ __align__(128) float g_bufD[(size_t)B * F * 64 * 64];
__device__ float g_mean[B * F];
__device__ float g_rstd[B * F];

// ---------------------------------------------------------------------------
// Packed f32x2 helpers
// ---------------------------------------------------------------------------
__device__ __forceinline__ u64 pack2(float v) {
    u64 r;
    asm("mov.b64 %0, {%1, %1};" : "=l"(r) : "f"(v));
    return r;
}
__device__ __forceinline__ void fma2(u64& acc, u64 a, u64 b) {
    asm("fma.rn.f32x2 %0, %1, %2, %0;" : "+l"(acc) : "l"(a), "l"(b));
}
__device__ __forceinline__ float2 unpack2(u64 v) {
    float2 r;
    asm("mov.b64 {%0, %1}, %2;" : "=f"(r.x), "=f"(r.y) : "l"(v));
    return r;
}

// ---------------------------------------------------------------------------
// Instance-norm statistics
// ---------------------------------------------------------------------------
__global__ void in_stats_kernel(const float* __restrict__ in, int HW,
                                float* __restrict__ mean, float* __restrict__ rstd)
{
    int bc = blockIdx.x;
    const float4* p = (const float4*)(in + (size_t)bc * HW);
    int n4 = HW >> 2;
    float s1 = 0.f, s2 = 0.f;
    for (int i = threadIdx.x; i < n4; i += blockDim.x) {
        float4 v = p[i];
        s1 += v.x + v.y + v.z + v.w;
        s2 += v.x * v.x + v.y * v.y + v.z * v.z + v.w * v.w;
    }
    __shared__ float sh1[32], sh2[32];
    #pragma unroll
    for (int o = 16; o; o >>= 1) {
        s1 += __shfl_down_sync(0xffffffffu, s1, o);
        s2 += __shfl_down_sync(0xffffffffu, s2, o);
    }
    int lane = threadIdx.x & 31, w = threadIdx.x >> 5;
    if (lane == 0) { sh1[w] = s1; sh2[w] = s2; }
    __syncthreads();
    if (w == 0) {
        int nw = blockDim.x >> 5;
        s1 = lane < nw ? sh1[lane] : 0.f;
        s2 = lane < nw ? sh2[lane] : 0.f;
        #pragma unroll
        for (int o = 16; o; o >>= 1) {
            s1 += __shfl_down_sync(0xffffffffu, s1, o);
            s2 += __shfl_down_sync(0xffffffffu, s2, o);
        }
        if (lane == 0) {
            float m = s1 / (float)HW;
            float var = s2 / (float)HW - m * m;
            mean[bc] = m;
            rstd[bc] = rsqrtf(var + 1e-5f);
        }
    }
}

// ---------------------------------------------------------------------------
// conv1: 7x7 s2 p3, Cin=3 (IN fused), Cout=32.  [64,3,256,256]->[64,32,128,128]
// Duplicated-input smem: s_in stores float2{v,v}; inputs load as LDS.64/128.
// Dynamic smem: s_w (18816 B) + s_in (3*37*38 float2 = 33744 B) = 52560 B.
// ---------------------------------------------------------------------------
__global__ void conv1_kernel(const float* __restrict__ x,
                             const float* __restrict__ w,      // [32][3][7][7]
                             const float* __restrict__ bias,
                             const float* __restrict__ mean,
                             const float* __restrict__ rstd,
                             float* __restrict__ out)
{
    extern __shared__ float sm[];
    float*  s_w  = sm;                       // [c*49+k][32]
    float2* s_in = (float2*)(sm + 147 * 32); // [3][37][38] dup pairs

    int b = blockIdx.z;
    int oh0 = blockIdx.y * 16, ow0 = blockIdx.x * 16;
    int tid = threadIdx.x;

    for (int i = tid; i < 32 * 147; i += 256) {
        int f = i / 147, ck = i - f * 147;
        s_w[ck * 32 + f] = w[i];
    }
    int ih0 = oh0 * 2 - 3, iw0 = ow0 * 2 - 3;
    for (int c = 0; c < 3; c++) {
        int bc = b * 3 + c;
        float m = mean[bc], r = rstd[bc];
        const float* xp = x + (size_t)bc * 65536;
        for (int i = tid; i < 37 * 37; i += 256) {
            int rr = i / 37, cc = i - rr * 37;
            int ih = ih0 + rr, iw = iw0 + cc;
            float v = 0.f;
            if ((unsigned)ih < 256u && (unsigned)iw < 256u)
                v = (xp[ih * 256 + iw] - m) * r;
            s_in[(c * 37 + rr) * 38 + cc] = make_float2(v, v);
        }
    }
    __syncthreads();

    const int fg = tid >> 6;
    const int pg = tid & 63;
    const int prow = pg >> 2;
    const int pc0 = (pg & 3) * 4;
    const int f0 = fg * 8;

    u64 acc2[4][4];
    #pragma unroll
    for (int p = 0; p < 4; p++)
        #pragma unroll
        for (int q = 0; q < 4; q++) acc2[p][q] = 0ull;

    for (int c = 0; c < 3; c++) {
        #pragma unroll 1
        for (int kh = 0; kh < 7; kh++) {
            const float2* rowp = s_in + (c * 37 + prow * 2 + kh) * 38 + pc0 * 2;
            u64 rv2[13];
            #pragma unroll
            for (int i = 0; i < 6; i++) {
                ulonglong2 t = *(const ulonglong2*)(rowp + 2 * i);
                rv2[2 * i] = t.x; rv2[2 * i + 1] = t.y;
            }
            rv2[12] = *(const u64*)(rowp + 12);
            #pragma unroll
            for (int kw = 0; kw < 7; kw++) {
                const ulonglong2* wp = (const ulonglong2*)(s_w + (c * 49 + kh * 7 + kw) * 32 + f0);
                ulonglong2 wA = wp[0], wB = wp[1];
                #pragma unroll
                for (int p = 0; p < 4; p++) {
                    u64 vv = rv2[2 * p + kw];
                    fma2(acc2[p][0], vv, wA.x);
                    fma2(acc2[p][1], vv, wA.y);
                    fma2(acc2[p][2], vv, wB.x);
                    fma2(acc2[p][3], vv, wB.y);
                }
            }
        }
    }
    int oh = oh0 + prow;
    int owb = ow0 + pc0;
    #pragma unroll
    for (int q = 0; q < 4; q++) {
        float2 u0 = unpack2(acc2[0][q]), u1 = unpack2(acc2[1][q]);
        float2 u2 = unpack2(acc2[2][q]), u3 = unpack2(acc2[3][q]);
        int f = f0 + 2 * q;
        float bv0 = bias[f], bv1 = bias[f + 1];
        size_t idx0 = (((size_t)(b * 32 + f) * 128) + oh) * 128 + owb;
        size_t idx1 = idx0 + (size_t)128 * 128;
        float4 r0 = { u0.x + bv0, u1.x + bv0, u2.x + bv0, u3.x + bv0 };
        float4 r1 = { u0.y + bv1, u1.y + bv1, u2.y + bv1, u3.y + bv1 };
        *(float4*)(out + idx0) = r0;
        *(float4*)(out + idx1) = r1;
    }
}

// ---------------------------------------------------------------------------
// 3x3 conv 32->32, stride S, pad 1, IN+ReLU fused on load, optional residual.
// Duplicated-input smem (float2{v,v}) -> all inner-loop smem reads are 64/128b.
// S=2: CHUNK=4 (72768 B, 3 CTAs)   S=1: CHUNK=8 (59904 B, 3 CTAs)
// ---------------------------------------------------------------------------
template<int S, int IH>
__global__ void conv3_kernel(const float* __restrict__ in,
                             const float* __restrict__ w,      // [32][32][3][3]
                             const float* __restrict__ bias,
                             const float* __restrict__ mean,
                             const float* __restrict__ rstd,
                             const float* __restrict__ add,    // may be null
                             float* __restrict__ out)
{
    constexpr int IW = IH;
    constexpr int OH = IH / S;
    constexpr int OW = OH;
    constexpr int ITH = 16 * S + (3 - S);          // 18 / 33
    constexpr int ITW = ITH;
    constexpr int ITWP = (S == 2) ? 34 : 20;       // even padded (float2 units)
    constexpr int CHUNK = (S == 2) ? 4 : 8;
    constexpr int NCHUNK = 32 / CHUNK;
    constexpr int RVN = 3 + 3 * S;                 // 6 / 9

    extern __shared__ float sm[];
    float*  s_w  = sm;                      // 9216 floats [(c*9+k)*32+f]
    float2* s_in = (float2*)(sm + 9216);    // [CHUNK][ITH][ITWP] dup pairs
    __shared__ float s_m[32], s_r[32];

    int b = blockIdx.z;
    int oh0 = blockIdx.y * 16, ow0 = blockIdx.x * 16;
    int tid = threadIdx.x;

    for (int i = tid; i < 9216; i += 256) {
        int f = i / 288, ck = i - f * 288;
        s_w[ck * 32 + f] = w[i];
    }
    if (tid < 32) { s_m[tid] = mean[b * 32 + tid]; s_r[tid] = rstd[b * 32 + tid]; }

    const int fg = tid >> 6;
    const int pg = tid & 63;
    const int prow = pg >> 2;
    const int pc0 = (pg & 3) * 4;
    const int f0 = fg * 8;

    u64 acc2[4][4];
    #pragma unroll
    for (int p = 0; p < 4; p++)
        #pragma unroll
        for (int q = 0; q < 4; q++) acc2[p][q] = 0ull;

    const int ih0 = oh0 * S - 1, iw0 = ow0 * S - 1;

    for (int chunk = 0; chunk < NCHUNK; chunk++) {
        __syncthreads();
        for (int i = tid; i < CHUNK * ITH * ITW; i += 256) {
            int ci = i / (ITH * ITW);
            int rem = i - ci * (ITH * ITW);
            int rr = rem / ITW, cc = rem - rr * ITW;
            int c = chunk * CHUNK + ci;
            int ih = ih0 + rr, iw = iw0 + cc;
            float v = 0.f;
            if ((unsigned)ih < (unsigned)IH && (unsigned)iw < (unsigned)IW) {
                float t = (in[(size_t)(b * 32 + c) * (IH * IW) + ih * IW + iw] - s_m[c]) * s_r[c];
                v = fmaxf(t, 0.f);
            }
            s_in[(ci * ITH + rr) * ITWP + cc] = make_float2(v, v);
        }
        __syncthreads();

        #pragma unroll 1
        for (int ci = 0; ci < CHUNK; ci++) {
            const float* wbase = s_w + ((chunk * CHUNK + ci) * 9) * 32 + f0;
            #pragma unroll
            for (int kh = 0; kh < 3; kh++) {
                const float2* rowp = s_in + (ci * ITH + prow * S + kh) * ITWP + pc0 * S;
                u64 rv2[RVN];
                #pragma unroll
                for (int i = 0; i < RVN / 2; i++) {
                    ulonglong2 t = *(const ulonglong2*)(rowp + 2 * i);
                    rv2[2 * i] = t.x; rv2[2 * i + 1] = t.y;
                }
                if (RVN & 1) rv2[RVN - 1] = *(const u64*)(rowp + RVN - 1);
                #pragma unroll
                for (int kw = 0; kw < 3; kw++) {
                    const ulonglong2* wp = (const ulonglong2*)(wbase + (kh * 3 + kw) * 32);
                    ulonglong2 wA = wp[0], wB = wp[1];
                    #pragma unroll
                    for (int p = 0; p < 4; p++) {
                        u64 vv = rv2[p * S + kw];
                        fma2(acc2[p][0], vv, wA.x);
                        fma2(acc2[p][1], vv, wA.y);
                        fma2(acc2[p][2], vv, wB.x);
                        fma2(acc2[p][3], vv, wB.y);
                    }
                }
            }
        }
    }

    int oh = oh0 + prow;
    int owb = ow0 + pc0;
    #pragma unroll
    for (int q = 0; q < 4; q++) {
        float2 u0 = unpack2(acc2[0][q]), u1 = unpack2(acc2[1][q]);
        float2 u2 = unpack2(acc2[2][q]), u3 = unpack2(acc2[3][q]);
        int f = f0 + 2 * q;
        float bv0 = bias[f], bv1 = bias[f + 1];
        size_t idx0 = (((size_t)(b * 32 + f) * OH) + oh) * OW + owb;
        size_t idx1 = idx0 + (size_t)OH * OW;
        float4 r0 = { u0.x + bv0, u1.x + bv0, u2.x + bv0, u3.x + bv0 };
        float4 r1 = { u0.y + bv1, u1.y + bv1, u2.y + bv1, u3.y + bv1 };
        if (add) {
            float4 a0 = *(const float4*)(add + idx0);
            float4 a1 = *(const float4*)(add + idx1);
            r0.x += a0.x; r0.y += a0.y; r0.z += a0.z; r0.w += a0.w;
            r1.x += a1.x; r1.y += a1.y; r1.z += a1.z; r1.w += a1.w;
        }
        *(float4*)(out + idx0) = r0;
        *(float4*)(out + idx1) = r1;
    }
}

// ---------------------------------------------------------------------------
// 1x1 stride-2 skip projection (raw input, bias), packed FFMA2.
// ---------------------------------------------------------------------------
template<int IH>
__global__ void skip1x1_kernel(const float* __restrict__ in,
                               const float* __restrict__ w,     // [32][32]
                               const float* __restrict__ bias,
                               float* __restrict__ out)
{
    constexpr int IW = IH;
    constexpr int OH = IH / 2;
    constexpr int OW = OH;
    __shared__ __align__(16) float s_w[32 * 32];
    int b = blockIdx.z;
    int oh0 = blockIdx.y * 16, ow0 = blockIdx.x * 16;
    int tid = threadIdx.x;
    for (int i = tid; i < 1024; i += 256) {
        int f = i >> 5, c = i & 31;
        s_w[c * 32 + f] = w[i];
    }
    __syncthreads();
    int ty = tid >> 4, tx = tid & 15;
    int oh = oh0 + ty, ow = ow0 + tx;
    int ih = oh * 2, iw = ow * 2;
    u64 acc2[16];
    #pragma unroll
    for (int q = 0; q < 16; q++) acc2[q] = 0ull;
    #pragma unroll 4
    for (int c = 0; c < 32; c++) {
        u64 vv = pack2(in[((size_t)(b * 32 + c) * IH + ih) * IW + iw]);
        const ulonglong2* wp = (const ulonglong2*)(s_w + c * 32);
        #pragma unroll
        for (int q = 0; q < 8; q++) {
            ulonglong2 wv = wp[q];
            fma2(acc2[2 * q], vv, wv.x);
            fma2(acc2[2 * q + 1], vv, wv.y);
        }
    }
    #pragma unroll
    for (int q = 0; q < 16; q++) {
        float2 u = unpack2(acc2[q]);
        int f = 2 * q;
        out[((size_t)(b * 32 + f) * OH + oh) * OW + ow]     = u.x + bias[f];
        out[((size_t)(b * 32 + f + 1) * OH + oh) * OW + ow] = u.y + bias[f + 1];
    }
}

// ---------------------------------------------------------------------------
// Fused attention + final linear: one block per batch sample.
// ---------------------------------------------------------------------------
__global__ void attn_kernel(const float* __restrict__ feat,
                            const float* __restrict__ text,
                            const float* __restrict__ attn_w,
                            const float* __restrict__ attn_b,
                            const float* __restrict__ final_w,
                            const float* __restrict__ final_b,
                            float* __restrict__ out)
{
    __shared__ __align__(16) float s_feat[32 * 256];
    __shared__ __align__(16) float s_text[256];
    __shared__ __align__(16) float s_a[5 * 256];
    __shared__ __align__(16) float s_probs[5 * 32];
    __shared__ __align__(16) float s_amap[5 * 256];

    int b = blockIdx.x;
    int tid = threadIdx.x;
    int warp = tid >> 5, lane = tid & 31;

    {
        const float4* fp = (const float4*)(feat + (size_t)b * 8192);
        float4* sp = (float4*)s_feat;
        for (int i = tid; i < 2048; i += 256) sp[i] = fp[i];
        s_text[tid] = text[b * 256 + tid];
    }
    __syncthreads();

    const float4* st4 = (const float4*)s_text;
    for (int row = warp; row < 1280; row += 8) {
        const float4* wr = (const float4*)(attn_w + (size_t)row * 256);
        float s = 0.f;
        #pragma unroll
        for (int t4 = lane; t4 < 64; t4 += 32) {
            float4 wv = wr[t4];
            float4 tv = st4[t4];
            s += wv.x * tv.x + wv.y * tv.y + wv.z * tv.z + wv.w * tv.w;
        }
        #pragma unroll
        for (int o = 16; o; o >>= 1) s += __shfl_down_sync(0xffffffffu, s, o);
        if (lane == 0) {
            float v = s + attn_b[row];
            s_a[row] = 1.f / (1.f + expf(-v));
        }
    }
    __syncthreads();

    for (int row = warp; row < 160; row += 8) {
        int h = row >> 5, c = row & 31;
        float s = 0.f;
        for (int ij = lane; ij < 256; ij += 32)
            s += s_a[h * 256 + ij] * s_feat[c * 256 + ij];
        #pragma unroll
        for (int o = 16; o; o >>= 1) s += __shfl_down_sync(0xffffffffu, s, o);
        if (lane == 0) s_probs[row] = s;
    }
    __syncthreads();

    if (warp < 5) {
        float v = s_probs[warp * 32 + lane];
        float mx = v;
        #pragma unroll
        for (int o = 16; o; o >>= 1) mx = fmaxf(mx, __shfl_xor_sync(0xffffffffu, mx, o));
        float e = expf(v - mx);
        float sum = e;
        #pragma unroll
        for (int o = 16; o; o >>= 1) sum += __shfl_xor_sync(0xffffffffu, sum, o);
        s_probs[warp * 32 + lane] = e / sum;
    }
    __syncthreads();

    for (int i = tid; i < 1280; i += 256) {
        int h = i >> 8, ij = i & 255;
        float s = 0.f;
        #pragma unroll
        for (int c = 0; c < 32; c++)
            s += s_probs[h * 32 + c] * s_feat[c * 256 + ij];
        s_amap[i] = s;
    }
    __syncthreads();

    const float4* am4 = (const float4*)s_amap;
    for (int row = warp; row < 512; row += 8) {
        const float4* wr = (const float4*)(final_w + (size_t)row * 1280);
        float s = 0.f;
        #pragma unroll
        for (int k4 = lane; k4 < 320; k4 += 32) {
            float4 wv = wr[k4];
            float4 av = am4[k4];
            s += wv.x * av.x + wv.y * av.y + wv.z * av.z + wv.w * av.w;
        }
        #pragma unroll
        for (int o = 16; o; o >>= 1) s += __shfl_down_sync(0xffffffffu, s, o);
        if (lane == 0) out[b * 512 + row] = s + final_b[row];
    }
}

// ---------------------------------------------------------------------------
// Host launch
// ---------------------------------------------------------------------------
extern "C" void kernel_launch(void* const* d_in, const int* in_sizes, int n_in,
                              void* d_out, int out_size)
{
    (void)in_sizes; (void)n_in; (void)out_size;
    const float* x       = (const float*)d_in[0];
    const float* text    = (const float*)d_in[1];
    const float* conv1_w = (const float*)d_in[2];
    const float* conv1_b = (const float*)d_in[3];
    const float* rbs_w1  = (const float*)d_in[4];
    const float* rbs_b1  = (const float*)d_in[5];
    const float* rbs_w2  = (const float*)d_in[6];
    const float* rbs_b2  = (const float*)d_in[7];
    const float* rbs_ws  = (const float*)d_in[8];
    const float* rbs_bs  = (const float*)d_in[9];
    const float* rb_w1   = (const float*)d_in[10];
    const float* rb_b1   = (const float*)d_in[11];
    const float* rb_w2   = (const float*)d_in[12];
    const float* rb_b2   = (const float*)d_in[13];
    const float* attn_w  = (const float*)d_in[14];
    const float* attn_b  = (const float*)d_in[15];
    const float* final_w = (const float*)d_in[16];
    const float* final_b = (const float*)d_in[17];
    float* out = (float*)d_out;

    float *f128, *bufA, *bufB, *bufC, *bufD, *mean, *rstd;
    cudaGetSymbolAddress((void**)&f128, g_f128);
    cudaGetSymbolAddress((void**)&bufA, g_bufA);
    cudaGetSymbolAddress((void**)&bufB, g_bufB);
    cudaGetSymbolAddress((void**)&bufC, g_bufC);
    cudaGetSymbolAddress((void**)&bufD, g_bufD);
    cudaGetSymbolAddress((void**)&mean, g_mean);
    cudaGetSymbolAddress((void**)&rstd, g_rstd);

    const int SM1 = 9216 * 4 + 8 * 18 * 20 * 8;   // 59904 B
    const int SM2 = 9216 * 4 + 4 * 33 * 34 * 8;   // 72768 B
    const int SMC = 147 * 32 * 4 + 3 * 37 * 38 * 8; // 52560 B
    cudaFuncSetAttribute(conv1_kernel,             cudaFuncAttributeMaxDynamicSharedMemorySize, SMC);
    cudaFuncSetAttribute(conv3_kernel<2, 128>, cudaFuncAttributeMaxDynamicSharedMemorySize, SM2);
    cudaFuncSetAttribute(conv3_kernel<2, 64>,  cudaFuncAttributeMaxDynamicSharedMemorySize, SM2);
    cudaFuncSetAttribute(conv3_kernel<2, 32>,  cudaFuncAttributeMaxDynamicSharedMemorySize, SM2);
    cudaFuncSetAttribute(conv3_kernel<1, 64>,  cudaFuncAttributeMaxDynamicSharedMemorySize, SM1);
    cudaFuncSetAttribute(conv3_kernel<1, 32>,  cudaFuncAttributeMaxDynamicSharedMemorySize, SM1);
    cudaFuncSetAttribute(conv3_kernel<1, 16>,  cudaFuncAttributeMaxDynamicSharedMemorySize, SM1);

    // stem: IN(x) -> conv1 (7x7 s2)
    in_stats_kernel<<<B * 3, 256>>>(x, 256 * 256, mean, rstd);
    conv1_kernel<<<dim3(8, 8, B), 256, SMC>>>(x, conv1_w, conv1_b, mean, rstd, f128);

    // strided block 0: 128 -> 64
    in_stats_kernel<<<B * F, 256>>>(f128, 128 * 128, mean, rstd);
    conv3_kernel<2, 128><<<dim3(4, 4, B), 256, SM2>>>(f128, rbs_w1, rbs_b1, mean, rstd, nullptr, bufA);
    skip1x1_kernel<128><<<dim3(4, 4, B), 256>>>(f128, rbs_ws, rbs_bs, bufB);
    in_stats_kernel<<<B * F, 256>>>(bufA, 64 * 64, mean, rstd);
    conv3_kernel<1, 64><<<dim3(4, 4, B), 256, SM1>>>(bufA, rbs_w2, rbs_b2, mean, rstd, bufB, bufC);

    // plain block 0 (64x64)
    in_stats_kernel<<<B * F, 256>>>(bufC, 64 * 64, mean, rstd);
    conv3_kernel<1, 64><<<dim3(4, 4, B), 256, SM1>>>(bufC, rb_w1, rb_b1, mean, rstd, nullptr, bufA);
    in_stats_kernel<<<B * F, 256>>>(bufA, 64 * 64, mean, rstd);
    conv3_kernel<1, 64><<<dim3(4, 4, B), 256, SM1>>>(bufA, rb_w2, rb_b2, mean, rstd, bufC, bufB);

    // strided block 1: 64 -> 32
    in_stats_kernel<<<B * F, 256>>>(bufB, 64 * 64, mean, rstd);
    conv3_kernel<2, 64><<<dim3(2, 2, B), 256, SM2>>>(bufB, rbs_w1 + 9216, rbs_b1 + 32, mean, rstd, nullptr, bufA);
    skip1x1_kernel<64><<<dim3(2, 2, B), 256>>>(bufB, rbs_ws + 1024, rbs_bs + 32, bufC);
    in_stats_kernel<<<B * F, 256>>>(bufA, 32 * 32, mean, rstd);
    conv3_kernel<1, 32><<<dim3(2, 2, B), 256, SM1>>>(bufA, rbs_w2 + 9216, rbs_b2 + 32, mean, rstd, bufC, bufD);

    // plain block 1 (32x32)
    in_stats_kernel<<<B * F, 256>>>(bufD, 32 * 32, mean, rstd);
    conv3_kernel<1, 32><<<dim3(2, 2, B), 256, SM1>>>(bufD, rb_w1 + 9216, rb_b1 + 32, mean, rstd, nullptr, bufA);
    in_stats_kernel<<<B * F, 256>>>(bufA, 32 * 32, mean, rstd);
    conv3_kernel<1, 32><<<dim3(2, 2, B), 256, SM1>>>(bufA, rb_w2 + 9216, rb_b2 + 32, mean, rstd, bufD, bufB);

    // strided block 2: 32 -> 16
    in_stats_kernel<<<B * F, 256>>>(bufB, 32 * 32, mean, rstd);
    conv3_kernel<2, 32><<<dim3(1, 1, B), 256, SM2>>>(bufB, rbs_w1 + 18432, rbs_b1 + 64, mean, rstd, nullptr, bufA);
    skip1x1_kernel<32><<<dim3(1, 1, B), 256>>>(bufB, rbs_ws + 2048, rbs_bs + 64, bufC);
    in_stats_kernel<<<B * F, 256>>>(bufA, 16 * 16, mean, rstd);
    conv3_kernel<1, 16><<<dim3(1, 1, B), 256, SM1>>>(bufA, rbs_w2 + 18432, rbs_b2 + 64, mean, rstd, bufC, bufD);

    // fused attention + final projection
    attn_kernel<<<B, 256>>>(bufD, text, attn_w, attn_b, final_w, final_b, out);
}

// round 12
// speedup vs baseline: 1.0563x; 1.0563x over previous
#include <cuda_runtime.h>
#include <cuda_bf16.h>
#include <math.h>

#define B 64
#define F 32

typedef unsigned long long u64;

__device__ __align__(128) float g_f128[(size_t)B * F * 128 * 128];
__device__ __align__(128) float g_bufA[(size_t)B * F * 64 * 64];
__device__ __align__(128) float g_bufB[(size_t)B * F * 64 * 64];
__device__ __align__(128) float g_bufC[(size_t)B * F * 64 * 64];
__device__ __align__(128) float g_bufD[(size_t)B * F * 64 * 64];
__device__ float g_mean[B * F];
__device__ float g_rstd[B * F];

// ---------------------------------------------------------------------------
// Packed f32x2 helpers
// ---------------------------------------------------------------------------
__device__ __forceinline__ u64 pack2(float v) {
    u64 r;
    asm("mov.b64 %0, {%1, %1};" : "=l"(r) : "f"(v));
    return r;
}
__device__ __forceinline__ void fma2(u64& acc, u64 a, u64 b) {
    asm("fma.rn.f32x2 %0, %1, %2, %0;" : "+l"(acc) : "l"(a), "l"(b));
}
__device__ __forceinline__ float2 unpack2(u64 v) {
    float2 r;
    asm("mov.b64 {%0, %1}, %2;" : "=f"(r.x), "=f"(r.y) : "l"(v));
    return r;
}

// ---------------------------------------------------------------------------
// Instance-norm statistics
// ---------------------------------------------------------------------------
__global__ void in_stats_kernel(const float* __restrict__ in, int HW,
                                float* __restrict__ mean, float* __restrict__ rstd)
{
    int bc = blockIdx.x;
    const float4* p = (const float4*)(in + (size_t)bc * HW);
    int n4 = HW >> 2;
    float s1 = 0.f, s2 = 0.f;
    for (int i = threadIdx.x; i < n4; i += blockDim.x) {
        float4 v = p[i];
        s1 += v.x + v.y + v.z + v.w;
        s2 += v.x * v.x + v.y * v.y + v.z * v.z + v.w * v.w;
    }
    __shared__ float sh1[32], sh2[32];
    #pragma unroll
    for (int o = 16; o; o >>= 1) {
        s1 += __shfl_down_sync(0xffffffffu, s1, o);
        s2 += __shfl_down_sync(0xffffffffu, s2, o);
    }
    int lane = threadIdx.x & 31, w = threadIdx.x >> 5;
    if (lane == 0) { sh1[w] = s1; sh2[w] = s2; }
    __syncthreads();
    if (w == 0) {
        int nw = blockDim.x >> 5;
        s1 = lane < nw ? sh1[lane] : 0.f;
        s2 = lane < nw ? sh2[lane] : 0.f;
        #pragma unroll
        for (int o = 16; o; o >>= 1) {
            s1 += __shfl_down_sync(0xffffffffu, s1, o);
            s2 += __shfl_down_sync(0xffffffffu, s2, o);
        }
        if (lane == 0) {
            float m = s1 / (float)HW;
            float var = s2 / (float)HW - m * m;
            mean[bc] = m;
            rstd[bc] = rsqrtf(var + 1e-5f);
        }
    }
}

// ---------------------------------------------------------------------------
// conv1: 7x7 s2 p3, Cin=3 (IN fused), Cout=32  (round-10 proven version)
// ---------------------------------------------------------------------------
__global__ void conv1_kernel(const float* __restrict__ x,
                             const float* __restrict__ w,
                             const float* __restrict__ bias,
                             const float* __restrict__ mean,
                             const float* __restrict__ rstd,
                             float* __restrict__ out)
{
    __shared__ __align__(16) float s_w[147][32];
    __shared__ __align__(16) float s_in[3][37][38];
    int b = blockIdx.z;
    int oh0 = blockIdx.y * 16, ow0 = blockIdx.x * 16;
    int tid = threadIdx.x;

    for (int i = tid; i < 32 * 147; i += 256) {
        int f = i / 147, ck = i - f * 147;
        s_w[ck][f] = w[i];
    }
    int ih0 = oh0 * 2 - 3, iw0 = ow0 * 2 - 3;
    for (int c = 0; c < 3; c++) {
        int bc = b * 3 + c;
        float m = mean[bc], r = rstd[bc];
        const float* xp = x + (size_t)bc * 65536;
        for (int i = tid; i < 37 * 37; i += 256) {
            int rr = i / 37, cc = i - rr * 37;
            int ih = ih0 + rr, iw = iw0 + cc;
            float v = 0.f;
            if ((unsigned)ih < 256u && (unsigned)iw < 256u)
                v = (xp[ih * 256 + iw] - m) * r;
            s_in[c][rr][cc] = v;
        }
    }
    __syncthreads();

    const int fg = tid >> 6;
    const int pg = tid & 63;
    const int prow = pg >> 2;
    const int pc0 = (pg & 3) * 4;
    const int f0 = fg * 8;

    u64 acc2[4][4];
    #pragma unroll
    for (int p = 0; p < 4; p++)
        #pragma unroll
        for (int q = 0; q < 4; q++) acc2[p][q] = 0ull;

    for (int c = 0; c < 3; c++) {
        #pragma unroll 1
        for (int kh = 0; kh < 7; kh++) {
            const float* rowp = &s_in[c][prow * 2 + kh][pc0 * 2];
            u64 rv2[13];
            #pragma unroll
            for (int i = 0; i < 13; i++) rv2[i] = pack2(rowp[i]);
            #pragma unroll
            for (int kw = 0; kw < 7; kw++) {
                const u64* wp = (const u64*)&s_w[c * 49 + kh * 7 + kw][f0];
                u64 w0 = wp[0], w1 = wp[1], w2 = wp[2], w3 = wp[3];
                #pragma unroll
                for (int p = 0; p < 4; p++) {
                    u64 vv = rv2[2 * p + kw];
                    fma2(acc2[p][0], vv, w0);
                    fma2(acc2[p][1], vv, w1);
                    fma2(acc2[p][2], vv, w2);
                    fma2(acc2[p][3], vv, w3);
                }
            }
        }
    }
    int oh = oh0 + prow;
    int owb = ow0 + pc0;
    #pragma unroll
    for (int q = 0; q < 4; q++) {
        float2 u0 = unpack2(acc2[0][q]), u1 = unpack2(acc2[1][q]);
        float2 u2 = unpack2(acc2[2][q]), u3 = unpack2(acc2[3][q]);
        int f = f0 + 2 * q;
        float bv0 = bias[f], bv1 = bias[f + 1];
        size_t idx0 = (((size_t)(b * 32 + f) * 128) + oh) * 128 + owb;
        size_t idx1 = idx0 + (size_t)128 * 128;
        float4 r0 = { u0.x + bv0, u1.x + bv0, u2.x + bv0, u3.x + bv0 };
        float4 r1 = { u0.y + bv1, u1.y + bv1, u2.y + bv1, u3.y + bv1 };
        *(float4*)(out + idx0) = r0;
        *(float4*)(out + idx1) = r1;
    }
}

// ---------------------------------------------------------------------------
// S=2 3x3 conv (round-10 proven version): 256 threads, 4px x 8f, CHUNK=8.
// ---------------------------------------------------------------------------
template<int IH>
__global__ void conv3s2_kernel(const float* __restrict__ in,
                               const float* __restrict__ w,
                               const float* __restrict__ bias,
                               const float* __restrict__ mean,
                               const float* __restrict__ rstd,
                               const float* __restrict__ add,
                               float* __restrict__ out)
{
    constexpr int IW = IH;
    constexpr int OH = IH / 2;
    constexpr int OW = OH;
    constexpr int ITH = 33, ITW = 33, ITWP = 35;
    constexpr int CHUNK = 8;
    constexpr int NCHUNK = 4;

    extern __shared__ float sm[];
    float* s_w = sm;
    float* s_in = sm + 9216;
    __shared__ float s_m[32], s_r[32];

    int b = blockIdx.z;
    int oh0 = blockIdx.y * 16, ow0 = blockIdx.x * 16;
    int tid = threadIdx.x;

    for (int i = tid; i < 9216; i += 256) {
        int f = i / 288, ck = i - f * 288;
        s_w[ck * 32 + f] = w[i];
    }
    if (tid < 32) { s_m[tid] = mean[b * 32 + tid]; s_r[tid] = rstd[b * 32 + tid]; }

    const int fg = tid >> 6;
    const int pg = tid & 63;
    const int prow = pg >> 2;
    const int pc0 = (pg & 3) * 4;
    const int f0 = fg * 8;

    u64 acc2[4][4];
    #pragma unroll
    for (int p = 0; p < 4; p++)
        #pragma unroll
        for (int q = 0; q < 4; q++) acc2[p][q] = 0ull;

    const int ih0 = oh0 * 2 - 1, iw0 = ow0 * 2 - 1;

    for (int chunk = 0; chunk < NCHUNK; chunk++) {
        __syncthreads();
        for (int i = tid; i < CHUNK * ITH * ITW; i += 256) {
            int ci = i / (ITH * ITW);
            int rem = i - ci * (ITH * ITW);
            int rr = rem / ITW, cc = rem - rr * ITW;
            int c = chunk * CHUNK + ci;
            int ih = ih0 + rr, iw = iw0 + cc;
            float v = 0.f;
            if ((unsigned)ih < (unsigned)IH && (unsigned)iw < (unsigned)IW) {
                float t = (in[(size_t)(b * 32 + c) * (IH * IW) + ih * IW + iw] - s_m[c]) * s_r[c];
                v = fmaxf(t, 0.f);
            }
            s_in[(ci * ITH + rr) * ITWP + cc] = v;
        }
        __syncthreads();

        #pragma unroll 1
        for (int ci = 0; ci < CHUNK; ci++) {
            const float* wbase = s_w + ((chunk * CHUNK + ci) * 9) * 32 + f0;
            #pragma unroll
            for (int kh = 0; kh < 3; kh++) {
                const float* rowp = s_in + (ci * ITH + prow * 2 + kh) * ITWP + pc0 * 2;
                u64 rv2[9];
                #pragma unroll
                for (int i = 0; i < 9; i++) rv2[i] = pack2(rowp[i]);
                #pragma unroll
                for (int kw = 0; kw < 3; kw++) {
                    const u64* wp = (const u64*)(wbase + (kh * 3 + kw) * 32);
                    u64 w0 = wp[0], w1 = wp[1], w2 = wp[2], w3 = wp[3];
                    #pragma unroll
                    for (int p = 0; p < 4; p++) {
                        u64 vv = rv2[p * 2 + kw];
                        fma2(acc2[p][0], vv, w0);
                        fma2(acc2[p][1], vv, w1);
                        fma2(acc2[p][2], vv, w2);
                        fma2(acc2[p][3], vv, w3);
                    }
                }
            }
        }
    }

    int oh = oh0 + prow;
    int owb = ow0 + pc0;
    #pragma unroll
    for (int q = 0; q < 4; q++) {
        float2 u0 = unpack2(acc2[0][q]), u1 = unpack2(acc2[1][q]);
        float2 u2 = unpack2(acc2[2][q]), u3 = unpack2(acc2[3][q]);
        int f = f0 + 2 * q;
        float bv0 = bias[f], bv1 = bias[f + 1];
        size_t idx0 = (((size_t)(b * 32 + f) * OH) + oh) * OW + owb;
        size_t idx1 = idx0 + (size_t)OH * OW;
        float4 r0 = { u0.x + bv0, u1.x + bv0, u2.x + bv0, u3.x + bv0 };
        float4 r1 = { u0.y + bv1, u1.y + bv1, u2.y + bv1, u3.y + bv1 };
        if (add) {
            float4 a0 = *(const float4*)(add + idx0);
            float4 a1 = *(const float4*)(add + idx1);
            r0.x += a0.x; r0.y += a0.y; r0.z += a0.z; r0.w += a0.w;
            r1.x += a1.x; r1.y += a1.y; r1.z += a1.z; r1.w += a1.w;
        }
        *(float4*)(out + idx0) = r0;
        *(float4*)(out + idx1) = r1;
    }
}

// ---------------------------------------------------------------------------
// NEW: S=1 3x3 conv, 128 threads, 8px x 8f register tile (32 u64 accs).
// fg = tid>>5 (channel group), pos = tid&31: prow 0..15, pc0 in {0,8}.
// ITWP=19 -> rv LDS.32 provably bank-conflict-free across the warp.
// smem = 9216*4 + 8*18*19*4 = 47808 B -> 4 CTAs/SM (launch_bounds 128,4).
// ---------------------------------------------------------------------------
template<int IH>
__global__ void __launch_bounds__(128, 4)
conv3s1_kernel(const float* __restrict__ in,
               const float* __restrict__ w,
               const float* __restrict__ bias,
               const float* __restrict__ mean,
               const float* __restrict__ rstd,
               const float* __restrict__ add,
               float* __restrict__ out)
{
    constexpr int IW = IH;
    constexpr int OH = IH, OW = IH;
    constexpr int ITH = 18, ITW = 18, ITWP = 19;
    constexpr int CHUNK = 8;
    constexpr int NCHUNK = 4;

    extern __shared__ float sm[];
    float* s_w = sm;                 // [(c*9+k)*32 + f]
    float* s_in = sm + 9216;         // [CHUNK][ITH][ITWP]
    __shared__ float s_m[32], s_r[32];

    int b = blockIdx.z;
    int oh0 = blockIdx.y * 16, ow0 = blockIdx.x * 16;
    int tid = threadIdx.x;

    for (int i = tid; i < 9216; i += 128) {
        int f = i / 288, ck = i - f * 288;
        s_w[ck * 32 + f] = w[i];
    }
    if (tid < 32) { s_m[tid] = mean[b * 32 + tid]; s_r[tid] = rstd[b * 32 + tid]; }

    const int fg = tid >> 5;            // 0..3 -> channel group
    const int pos = tid & 31;
    const int prow = pos >> 1;          // 0..15
    const int pc0 = (pos & 1) * 8;      // 0 or 8
    const int f0 = fg * 8;

    u64 acc2[8][4];
    #pragma unroll
    for (int p = 0; p < 8; p++)
        #pragma unroll
        for (int q = 0; q < 4; q++) acc2[p][q] = 0ull;

    const int ih0 = oh0 - 1, iw0 = ow0 - 1;

    for (int chunk = 0; chunk < NCHUNK; chunk++) {
        __syncthreads();
        for (int i = tid; i < CHUNK * ITH * ITW; i += 128) {
            int ci = i / (ITH * ITW);
            int rem = i - ci * (ITH * ITW);
            int rr = rem / ITW, cc = rem - rr * ITW;
            int c = chunk * CHUNK + ci;
            int ih = ih0 + rr, iw = iw0 + cc;
            float v = 0.f;
            if ((unsigned)ih < (unsigned)IH && (unsigned)iw < (unsigned)IW) {
                float t = (in[(size_t)(b * 32 + c) * (IH * IW) + ih * IW + iw] - s_m[c]) * s_r[c];
                v = fmaxf(t, 0.f);
            }
            s_in[(ci * ITH + rr) * ITWP + cc] = v;
        }
        __syncthreads();

        #pragma unroll 1
        for (int ci = 0; ci < CHUNK; ci++) {
            const float* wbase = s_w + ((chunk * CHUNK + ci) * 9) * 32 + f0;
            #pragma unroll
            for (int kh = 0; kh < 3; kh++) {
                const float* rowp = s_in + (ci * ITH + prow + kh) * ITWP + pc0;
                u64 rv2[10];
                #pragma unroll
                for (int i = 0; i < 10; i++) rv2[i] = pack2(rowp[i]);
                #pragma unroll
                for (int kw = 0; kw < 3; kw++) {
                    const u64* wp = (const u64*)(wbase + (kh * 3 + kw) * 32);
                    u64 w0 = wp[0], w1 = wp[1], w2 = wp[2], w3 = wp[3];
                    #pragma unroll
                    for (int p = 0; p < 8; p++) {
                        u64 vv = rv2[p + kw];
                        fma2(acc2[p][0], vv, w0);
                        fma2(acc2[p][1], vv, w1);
                        fma2(acc2[p][2], vv, w2);
                        fma2(acc2[p][3], vv, w3);
                    }
                }
            }
        }
    }

    int oh = oh0 + prow;
    int owb = ow0 + pc0;
    #pragma unroll
    for (int q = 0; q < 4; q++) {
        float2 u[8];
        #pragma unroll
        for (int p = 0; p < 8; p++) u[p] = unpack2(acc2[p][q]);
        int f = f0 + 2 * q;
        float bv0 = bias[f], bv1 = bias[f + 1];
        size_t idx0 = (((size_t)(b * 32 + f) * OH) + oh) * OW + owb;
        size_t idx1 = idx0 + (size_t)OH * OW;
        float4 r0a = { u[0].x + bv0, u[1].x + bv0, u[2].x + bv0, u[3].x + bv0 };
        float4 r0b = { u[4].x + bv0, u[5].x + bv0, u[6].x + bv0, u[7].x + bv0 };
        float4 r1a = { u[0].y + bv1, u[1].y + bv1, u[2].y + bv1, u[3].y + bv1 };
        float4 r1b = { u[4].y + bv1, u[5].y + bv1, u[6].y + bv1, u[7].y + bv1 };
        if (add) {
            float4 a0 = *(const float4*)(add + idx0);
            float4 a1 = *(const float4*)(add + idx0 + 4);
            float4 a2 = *(const float4*)(add + idx1);
            float4 a3 = *(const float4*)(add + idx1 + 4);
            r0a.x += a0.x; r0a.y += a0.y; r0a.z += a0.z; r0a.w += a0.w;
            r0b.x += a1.x; r0b.y += a1.y; r0b.z += a1.z; r0b.w += a1.w;
            r1a.x += a2.x; r1a.y += a2.y; r1a.z += a2.z; r1a.w += a2.w;
            r1b.x += a3.x; r1b.y += a3.y; r1b.z += a3.z; r1b.w += a3.w;
        }
        *(float4*)(out + idx0)     = r0a;
        *(float4*)(out + idx0 + 4) = r0b;
        *(float4*)(out + idx1)     = r1a;
        *(float4*)(out + idx1 + 4) = r1b;
    }
}

// ---------------------------------------------------------------------------
// 1x1 stride-2 skip projection (raw input, bias), packed FFMA2.
// ---------------------------------------------------------------------------
template<int IH>
__global__ void skip1x1_kernel(const float* __restrict__ in,
                               const float* __restrict__ w,
                               const float* __restrict__ bias,
                               float* __restrict__ out)
{
    constexpr int IW = IH;
    constexpr int OH = IH / 2;
    constexpr int OW = OH;
    __shared__ __align__(16) float s_w[32 * 32];
    int b = blockIdx.z;
    int oh0 = blockIdx.y * 16, ow0 = blockIdx.x * 16;
    int tid = threadIdx.x;
    for (int i = tid; i < 1024; i += 256) {
        int f = i >> 5, c = i & 31;
        s_w[c * 32 + f] = w[i];
    }
    __syncthreads();
    int ty = tid >> 4, tx = tid & 15;
    int oh = oh0 + ty, ow = ow0 + tx;
    int ih = oh * 2, iw = ow * 2;
    u64 acc2[16];
    #pragma unroll
    for (int q = 0; q < 16; q++) acc2[q] = 0ull;
    #pragma unroll 4
    for (int c = 0; c < 32; c++) {
        u64 vv = pack2(in[((size_t)(b * 32 + c) * IH + ih) * IW + iw]);
        const u64* wp = (const u64*)(s_w + c * 32);
        #pragma unroll
        for (int q = 0; q < 16; q++) fma2(acc2[q], vv, wp[q]);
    }
    #pragma unroll
    for (int q = 0; q < 16; q++) {
        float2 u = unpack2(acc2[q]);
        int f = 2 * q;
        out[((size_t)(b * 32 + f) * OH + oh) * OW + ow]     = u.x + bias[f];
        out[((size_t)(b * 32 + f + 1) * OH + oh) * OW + ow] = u.y + bias[f + 1];
    }
}

// ---------------------------------------------------------------------------
// Fused attention + final linear
// ---------------------------------------------------------------------------
__global__ void attn_kernel(const float* __restrict__ feat,
                            const float* __restrict__ text,
                            const float* __restrict__ attn_w,
                            const float* __restrict__ attn_b,
                            const float* __restrict__ final_w,
                            const float* __restrict__ final_b,
                            float* __restrict__ out)
{
    __shared__ __align__(16) float s_feat[32 * 256];
    __shared__ __align__(16) float s_text[256];
    __shared__ __align__(16) float s_a[5 * 256];
    __shared__ __align__(16) float s_probs[5 * 32];
    __shared__ __align__(16) float s_amap[5 * 256];

    int b = blockIdx.x;
    int tid = threadIdx.x;
    int warp = tid >> 5, lane = tid & 31;

    {
        const float4* fp = (const float4*)(feat + (size_t)b * 8192);
        float4* sp = (float4*)s_feat;
        for (int i = tid; i < 2048; i += 256) sp[i] = fp[i];
        s_text[tid] = text[b * 256 + tid];
    }
    __syncthreads();

    const float4* st4 = (const float4*)s_text;
    for (int row = warp; row < 1280; row += 8) {
        const float4* wr = (const float4*)(attn_w + (size_t)row * 256);
        float s = 0.f;
        #pragma unroll
        for (int t4 = lane; t4 < 64; t4 += 32) {
            float4 wv = wr[t4];
            float4 tv = st4[t4];
            s += wv.x * tv.x + wv.y * tv.y + wv.z * tv.z + wv.w * tv.w;
        }
        #pragma unroll
        for (int o = 16; o; o >>= 1) s += __shfl_down_sync(0xffffffffu, s, o);
        if (lane == 0) {
            float v = s + attn_b[row];
            s_a[row] = 1.f / (1.f + expf(-v));
        }
    }
    __syncthreads();

    for (int row = warp; row < 160; row += 8) {
        int h = row >> 5, c = row & 31;
        float s = 0.f;
        for (int ij = lane; ij < 256; ij += 32)
            s += s_a[h * 256 + ij] * s_feat[c * 256 + ij];
        #pragma unroll
        for (int o = 16; o; o >>= 1) s += __shfl_down_sync(0xffffffffu, s, o);
        if (lane == 0) s_probs[row] = s;
    }
    __syncthreads();

    if (warp < 5) {
        float v = s_probs[warp * 32 + lane];
        float mx = v;
        #pragma unroll
        for (int o = 16; o; o >>= 1) mx = fmaxf(mx, __shfl_xor_sync(0xffffffffu, mx, o));
        float e = expf(v - mx);
        float sum = e;
        #pragma unroll
        for (int o = 16; o; o >>= 1) sum += __shfl_xor_sync(0xffffffffu, sum, o);
        s_probs[warp * 32 + lane] = e / sum;
    }
    __syncthreads();

    for (int i = tid; i < 1280; i += 256) {
        int h = i >> 8, ij = i & 255;
        float s = 0.f;
        #pragma unroll
        for (int c = 0; c < 32; c++)
            s += s_probs[h * 32 + c] * s_feat[c * 256 + ij];
        s_amap[i] = s;
    }
    __syncthreads();

    const float4* am4 = (const float4*)s_amap;
    for (int row = warp; row < 512; row += 8) {
        const float4* wr = (const float4*)(final_w + (size_t)row * 1280);
        float s = 0.f;
        #pragma unroll
        for (int k4 = lane; k4 < 320; k4 += 32) {
            float4 wv = wr[k4];
            float4 av = am4[k4];
            s += wv.x * av.x + wv.y * av.y + wv.z * av.z + wv.w * av.w;
        }
        #pragma unroll
        for (int o = 16; o; o >>= 1) s += __shfl_down_sync(0xffffffffu, s, o);
        if (lane == 0) out[b * 512 + row] = s + final_b[row];
    }
}

// ---------------------------------------------------------------------------
// Host launch
// ---------------------------------------------------------------------------
extern "C" void kernel_launch(void* const* d_in, const int* in_sizes, int n_in,
                              void* d_out, int out_size)
{
    (void)in_sizes; (void)n_in; (void)out_size;
    const float* x       = (const float*)d_in[0];
    const float* text    = (const float*)d_in[1];
    const float* conv1_w = (const float*)d_in[2];
    const float* conv1_b = (const float*)d_in[3];
    const float* rbs_w1  = (const float*)d_in[4];
    const float* rbs_b1  = (const float*)d_in[5];
    const float* rbs_w2  = (const float*)d_in[6];
    const float* rbs_b2  = (const float*)d_in[7];
    const float* rbs_ws  = (const float*)d_in[8];
    const float* rbs_bs  = (const float*)d_in[9];
    const float* rb_w1   = (const float*)d_in[10];
    const float* rb_b1   = (const float*)d_in[11];
    const float* rb_w2   = (const float*)d_in[12];
    const float* rb_b2   = (const float*)d_in[13];
    const float* attn_w  = (const float*)d_in[14];
    const float* attn_b  = (const float*)d_in[15];
    const float* final_w = (const float*)d_in[16];
    const float* final_b = (const float*)d_in[17];
    float* out = (float*)d_out;

    float *f128, *bufA, *bufB, *bufC, *bufD, *mean, *rstd;
    cudaGetSymbolAddress((void**)&f128, g_f128);
    cudaGetSymbolAddress((void**)&bufA, g_bufA);
    cudaGetSymbolAddress((void**)&bufB, g_bufB);
    cudaGetSymbolAddress((void**)&bufC, g_bufC);
    cudaGetSymbolAddress((void**)&bufD, g_bufD);
    cudaGetSymbolAddress((void**)&mean, g_mean);
    cudaGetSymbolAddress((void**)&rstd, g_rstd);

    const int SM1 = (9216 + 8 * 18 * 19) * 4;   // 47808 B -> 4 CTAs/SM
    const int SM2 = (9216 + 8 * 33 * 35) * 4;   // 73824 B -> 3 CTAs/SM
    cudaFuncSetAttribute(conv3s2_kernel<128>, cudaFuncAttributeMaxDynamicSharedMemorySize, SM2);
    cudaFuncSetAttribute(conv3s2_kernel<64>,  cudaFuncAttributeMaxDynamicSharedMemorySize, SM2);
    cudaFuncSetAttribute(conv3s2_kernel<32>,  cudaFuncAttributeMaxDynamicSharedMemorySize, SM2);
    cudaFuncSetAttribute(conv3s1_kernel<64>,  cudaFuncAttributeMaxDynamicSharedMemorySize, SM1);
    cudaFuncSetAttribute(conv3s1_kernel<32>,  cudaFuncAttributeMaxDynamicSharedMemorySize, SM1);
    cudaFuncSetAttribute(conv3s1_kernel<16>,  cudaFuncAttributeMaxDynamicSharedMemorySize, SM1);

    // stem: IN(x) -> conv1 (7x7 s2)
    in_stats_kernel<<<B * 3, 256>>>(x, 256 * 256, mean, rstd);
    conv1_kernel<<<dim3(8, 8, B), 256>>>(x, conv1_w, conv1_b, mean, rstd, f128);

    // strided block 0: 128 -> 64
    in_stats_kernel<<<B * F, 256>>>(f128, 128 * 128, mean, rstd);
    conv3s2_kernel<128><<<dim3(4, 4, B), 256, SM2>>>(f128, rbs_w1, rbs_b1, mean, rstd, nullptr, bufA);
    skip1x1_kernel<128><<<dim3(4, 4, B), 256>>>(f128, rbs_ws, rbs_bs, bufB);
    in_stats_kernel<<<B * F, 256>>>(bufA, 64 * 64, mean, rstd);
    conv3s1_kernel<64><<<dim3(4, 4, B), 128, SM1>>>(bufA, rbs_w2, rbs_b2, mean, rstd, bufB, bufC);

    // plain block 0 (64x64)
    in_stats_kernel<<<B * F, 256>>>(bufC, 64 * 64, mean, rstd);
    conv3s1_kernel<64><<<dim3(4, 4, B), 128, SM1>>>(bufC, rb_w1, rb_b1, mean, rstd, nullptr, bufA);
    in_stats_kernel<<<B * F, 256>>>(bufA, 64 * 64, mean, rstd);
    conv3s1_kernel<64><<<dim3(4, 4, B), 128, SM1>>>(bufA, rb_w2, rb_b2, mean, rstd, bufC, bufB);

    // strided block 1: 64 -> 32
    in_stats_kernel<<<B * F, 256>>>(bufB, 64 * 64, mean, rstd);
    conv3s2_kernel<64><<<dim3(2, 2, B), 256, SM2>>>(bufB, rbs_w1 + 9216, rbs_b1 + 32, mean, rstd, nullptr, bufA);
    skip1x1_kernel<64><<<dim3(2, 2, B), 256>>>(bufB, rbs_ws + 1024, rbs_bs + 32, bufC);
    in_stats_kernel<<<B * F, 256>>>(bufA, 32 * 32, mean, rstd);
    conv3s1_kernel<32><<<dim3(2, 2, B), 128, SM1>>>(bufA, rbs_w2 + 9216, rbs_b2 + 32, mean, rstd, bufC, bufD);

    // plain block 1 (32x32)
    in_stats_kernel<<<B * F, 256>>>(bufD, 32 * 32, mean, rstd);
    conv3s1_kernel<32><<<dim3(2, 2, B), 128, SM1>>>(bufD, rb_w1 + 9216, rb_b1 + 32, mean, rstd, nullptr, bufA);
    in_stats_kernel<<<B * F, 256>>>(bufA, 32 * 32, mean, rstd);
    conv3s1_kernel<32><<<dim3(2, 2, B), 128, SM1>>>(bufA, rb_w2 + 9216, rb_b2 + 32, mean, rstd, bufD, bufB);

    // strided block 2: 32 -> 16
    in_stats_kernel<<<B * F, 256>>>(bufB, 32 * 32, mean, rstd);
    conv3s2_kernel<32><<<dim3(1, 1, B), 256, SM2>>>(bufB, rbs_w1 + 18432, rbs_b1 + 64, mean, rstd, nullptr, bufA);
    skip1x1_kernel<32><<<dim3(1, 1, B), 256>>>(bufB, rbs_ws + 2048, rbs_bs + 64, bufC);
    in_stats_kernel<<<B * F, 256>>>(bufA, 16 * 16, mean, rstd);
    conv3s1_kernel<16><<<dim3(1, 1, B), 128, SM1>>>(bufA, rbs_w2 + 18432, rbs_b2 + 64, mean, rstd, bufC, bufD);

    // fused attention + final projection
    attn_kernel<<<B, 256>>>(bufD, text, attn_w, attn_b, final_w, final_b, out);
}